// round 16
// baseline (speedup 1.0000x reference)
#include <cuda_runtime.h>
#include <cuda_bf16.h>
#include <mma.h>
#include <cstdint>

namespace wm = nvcuda::wmma;

#define BB   4
#define DIN_ 256
#define SS   2048
#define DMM  512
#define HH   8
#define DKK  64
#define NH   32                      // B*H
#define ZSIZE (BB*DIN_*SS)           // 2097152

typedef __nv_bfloat16 bf16;

// ---- device-global scratch (allocation-free rule) -------------------------
__device__ bf16  g_Qbh[NH*SS*DKK], g_Qbl[NH*SS*DKK];
__device__ bf16  g_Kbh[NH*SS*DKK], g_Kbl[NH*SS*DKK];
__device__ float g_V  [NH*SS*DKK];                      // tf32-rounded values
__device__ float g_AOh[SS*NH*DKK], g_AOl[SS*NH*DKK];    // flat [S][B*H][dk]
__device__ bf16  g_Wqbh[DMM*DIN_], g_Wqbl[DMM*DIN_];
__device__ bf16  g_Wkbh[DMM*DIN_], g_Wkbl[DMM*DIN_];
__device__ bf16  g_Wvbh[DMM*DIN_], g_Wvbl[DMM*DIN_];
__device__ float g_Woh[DIN_*DMM],  g_Wol[DIN_*DMM];

__device__ __forceinline__ float f2tf32(float x){
    float r; asm("cvt.rna.tf32.f32 %0, %1;" : "=f"(r) : "f"(x)); return r;
}

// bf16 fragments (m16n16k16)
using BFragA  = wm::fragment<wm::matrix_a,    16,16,16, bf16, wm::row_major>;
using BFragBc = wm::fragment<wm::matrix_b,    16,16,16, bf16, wm::col_major>;
using BFragC  = wm::fragment<wm::accumulator, 16,16,16, float>;
// tf32 fragments (m16n16k8)
using TFragA  = wm::fragment<wm::matrix_a,    16,16,8, wm::precision::tf32, wm::row_major>;
using TFragBc = wm::fragment<wm::matrix_b,    16,16,8, wm::precision::tf32, wm::col_major>;
using TFragBr = wm::fragment<wm::matrix_b,    16,16,8, wm::precision::tf32, wm::row_major>;
using TFragC  = wm::fragment<wm::accumulator, 16,16,8, float>;

// ---------------------------------------------------------------------------
// Kernel 0a/0b: weight splits.
// ---------------------------------------------------------------------------
__global__ void split_w_bf16(const float* __restrict__ s,
                             bf16* __restrict__ h, bf16* __restrict__ l, int n)
{
    int i = blockIdx.x * 256 + threadIdx.x;
    if (i < n){
        float v = s[i];
        bf16 hh = __float2bfloat16(v);
        h[i] = hh;
        l[i] = __float2bfloat16(v - __bfloat162float(hh));
    }
}
__global__ void split_w_f32(const float* __restrict__ s,
                            float* __restrict__ h, float* __restrict__ l, int n)
{
    int i = blockIdx.x * 256 + threadIdx.x;
    if (i < n){ float v = s[i]; float hh = f2tf32(v); h[i] = hh; l[i] = v - hh; }
}

// ---------------------------------------------------------------------------
// Kernel 1: QKV projections, bf16x2 (3-product) emulated fp32.  (unchanged)
//   V stored tf32-rounded (RNA) so PV can use it without cvt or lo-term.
// ---------------------------------------------------------------------------
__global__ void __launch_bounds__(256) qkv_kernel(
        const float* __restrict__ x,
        const float* __restrict__ bq, const float* __restrict__ bk,
        const float* __restrict__ bv)
{
    __shared__ __align__(16) char sraw[64*132*4];
    bf16*  shi  = (bf16*)sraw;
    bf16*  slo  = shi + 64*40;
    float* sC   = (float*)sraw;

    const int which = blockIdx.z;
    const bf16* Wh    = (which==0) ? g_Wqbh : (which==1 ? g_Wkbh : g_Wvbh);
    const bf16* Wl    = (which==0) ? g_Wqbl : (which==1 ? g_Wkbl : g_Wvbl);
    const float* bias = (which==0) ? bq    : (which==1 ? bk    : bv);

    const int r0 = blockIdx.x * 64;
    const int m0 = blockIdx.y * 128;
    const int s0 = r0 >> 2;
    const int t  = threadIdx.x;
    const int w  = t >> 5;
    const int wr = w >> 2;
    const int wc = w & 3;

    BFragC acc[2][2];
#pragma unroll
    for (int a=0;a<2;a++)
#pragma unroll
        for (int b2=0;b2<2;b2++) wm::fill_fragment(acc[a][b2], 0.0f);

    for (int kc = 0; kc < DIN_; kc += 32){
#pragma unroll
        for (int j = 0; j < 8; j++){
            int idx = j*256 + t;
            int sl  = idx & 15;
            int p   = idx >> 4;
            int bb  = p & 3;
            int il  = p >> 2;
            float v = x[bb*(DIN_*SS) + (kc+il)*SS + (s0+sl)];
            bf16 h  = __float2bfloat16(v);
            int pos = (sl*4 + bb)*40 + il;
            shi[pos] = h;
            slo[pos] = __float2bfloat16(v - __bfloat162float(h));
        }
        __syncthreads();

#pragma unroll
        for (int ks = 0; ks < 2; ks++){
            BFragA ahi[2], alo[2];
#pragma unroll
            for (int mt = 0; mt < 2; mt++){
                wm::load_matrix_sync(ahi[mt], shi + (wr*32 + mt*16)*40 + ks*16, 40);
                wm::load_matrix_sync(alo[mt], slo + (wr*32 + mt*16)*40 + ks*16, 40);
            }
#pragma unroll
            for (int nt = 0; nt < 2; nt++){
                BFragBc bhi, blo;
                const int wofs = (m0 + wc*32 + nt*16)*DIN_ + kc + ks*16;
                wm::load_matrix_sync(bhi, Wh + wofs, DIN_);
                wm::load_matrix_sync(blo, Wl + wofs, DIN_);
#pragma unroll
                for (int mt = 0; mt < 2; mt++){
                    wm::mma_sync(acc[mt][nt], ahi[mt], bhi, acc[mt][nt]);
                    wm::mma_sync(acc[mt][nt], ahi[mt], blo, acc[mt][nt]);
                    wm::mma_sync(acc[mt][nt], alo[mt], bhi, acc[mt][nt]);
                }
            }
        }
        __syncthreads();
    }

#pragma unroll
    for (int mt = 0; mt < 2; mt++)
#pragma unroll
        for (int nt = 0; nt < 2; nt++)
            wm::store_matrix_sync(sC + (wr*32 + mt*16)*132 + wc*32 + nt*16,
                                  acc[mt][nt], 132, wm::mem_row_major);
    __syncthreads();

#pragma unroll
    for (int it = 0; it < 32; it++){
        int rl = it*2 + (t >> 7);
        int ml = t & 127;
        int m  = m0 + ml;
        float v = sC[rl*132 + ml] + bias[m];
        int s  = s0 + (rl >> 2);
        int bb = rl & 3;
        int h  = m >> 6;
        int d  = m & 63;
        size_t o = (size_t)((bb*HH + h)*SS + s)*DKK + d;
        if (which == 2){
            g_V[o] = f2tf32(v);           // tf32-exact V for 1-term PV
        } else {
            bf16 hh = __float2bfloat16(v);
            bf16 ll = __float2bfloat16(v - __bfloat162float(hh));
            if (which == 0){ g_Qbh[o] = hh; g_Qbl[o] = ll; }
            else           { g_Kbh[o] = hh; g_Kbl[o] = ll; }
        }
    }
}

// ---------------------------------------------------------------------------
// Kernel 2a: scores = Q K^T (bf16x2, 3 MMA/k16).
//   A-fragments hoisted per k-step; epilogue staged via smem for fully
//   coalesced float4 stores of the raw-score block.
// CTA tile 128q x 128k, 8 warps.  grid (16,16,32), 72KB dyn smem, 2 CTA/SM.
// ---------------------------------------------------------------------------
#define SK_LD 72
__global__ void __launch_bounds__(256, 2) score_kernel(float* __restrict__ d_out)
{
    extern __shared__ __align__(16) bf16 sks[];
    bf16* sQh = sks;                    // [128][72]
    bf16* sQl = sQh + 128*SK_LD;
    bf16* sKh = sQl + 128*SK_LD;
    bf16* sKl = sKh + 128*SK_LD;
    float* sC = (float*)sks;            // epilogue reuse: [128][132]

    const int q0 = blockIdx.x * 128;
    const int k0 = blockIdx.y * 128;
    const int n  = blockIdx.z;
    const int t  = threadIdx.x;
    const int w  = t >> 5;
    const int wr = w >> 2;              // 0..1 -> 4 m-tiles each
    const int wc = w & 3;               // 0..3 -> 2 n-tiles each

    const bf16* Qhg = g_Qbh + ((size_t)n*SS + q0)*DKK;
    const bf16* Qlg = g_Qbl + ((size_t)n*SS + q0)*DKK;
    const bf16* Khg = g_Kbh + ((size_t)n*SS + k0)*DKK;
    const bf16* Klg = g_Kbl + ((size_t)n*SS + k0)*DKK;

#pragma unroll
    for (int i = 0; i < 4; i++){
        int idx = i*256 + t;            // 0..1023
        int r = idx >> 3, j = idx & 7;
        *(uint4*)(sQh + r*SK_LD + j*8) = *(const uint4*)(Qhg + r*DKK + j*8);
        *(uint4*)(sQl + r*SK_LD + j*8) = *(const uint4*)(Qlg + r*DKK + j*8);
        *(uint4*)(sKh + r*SK_LD + j*8) = *(const uint4*)(Khg + r*DKK + j*8);
        *(uint4*)(sKl + r*SK_LD + j*8) = *(const uint4*)(Klg + r*DKK + j*8);
    }
    __syncthreads();

    BFragC acc[4][2];
#pragma unroll
    for (int i=0;i<4;i++)
#pragma unroll
        for (int j=0;j<2;j++) wm::fill_fragment(acc[i][j], 0.0f);

#pragma unroll
    for (int ks = 0; ks < 4; ks++){
        BFragA ah[4], al[4];
#pragma unroll
        for (int i = 0; i < 4; i++){
            const int mtr = (wr*4 + i)*16;
            wm::load_matrix_sync(ah[i], sQh + mtr*SK_LD + ks*16, SK_LD);
            wm::load_matrix_sync(al[i], sQl + mtr*SK_LD + ks*16, SK_LD);
        }
#pragma unroll
        for (int j = 0; j < 2; j++){
            const int ntr = (wc*2 + j)*16;
            BFragBc bh, bl;
            wm::load_matrix_sync(bh, sKh + ntr*SK_LD + ks*16, SK_LD);
            wm::load_matrix_sync(bl, sKl + ntr*SK_LD + ks*16, SK_LD);
#pragma unroll
            for (int i = 0; i < 4; i++){
                wm::mma_sync(acc[i][j], ah[i], bh, acc[i][j]);
                wm::mma_sync(acc[i][j], ah[i], bl, acc[i][j]);
                wm::mma_sync(acc[i][j], al[i], bh, acc[i][j]);
            }
        }
    }
    __syncthreads();   // done reading staged tiles; reuse smem for C

#pragma unroll
    for (int i = 0; i < 4; i++)
#pragma unroll
        for (int j = 0; j < 2; j++)
            wm::store_matrix_sync(sC + (wr*4+i)*16*132 + (wc*2+j)*16,
                                  acc[i][j], 132, wm::mem_row_major);
    __syncthreads();

    // coalesced float4 write of the 128x128 raw-score block
    float* sco = d_out + (size_t)ZSIZE + (size_t)n*SS*SS + (size_t)q0*SS + k0;
#pragma unroll
    for (int it = 0; it < 16; it++){
        int idx = it*256 + t;           // 0..4095 float4
        int r = idx >> 5, c = idx & 31;
        *(float4*)(sco + (size_t)r*SS + c*4) = *(float4*)(sC + r*132 + c*4);
    }
}

// ---------------------------------------------------------------------------
// Kernel 2b: fused softmax + PV.  CTA = (head n, 128 q-rows), 256 threads.
//   Phase 1: warp w computes (max, 1/sum) for rows w*16..+15 -> smem stats.
//   Phase 2: per 128-col block: coalesced raw read, e=exp(s-m)*inv in regs,
//            coalesced attn_w write, tf32(e) into smem P; V staged in smem;
//            MMA fed entirely from smem (1 MMA/k8, V already tf32).
// grid (16 q-tiles, 32 heads), ~101KB dyn smem, 2 CTA/SM.
// ---------------------------------------------------------------------------
#define PV_PLD 132
#define PV_VLD 68
__global__ void __launch_bounds__(256) softpv_kernel(float* __restrict__ d_out)
{
    extern __shared__ __align__(16) float dsm[];
    float* sP = dsm;                      // [128][132]  P block (tf32)  / AO stage
    float* sV = dsm + 128*PV_PLD;         // [128][68]   V block
    float* sM = sV + 128*PV_VLD;          // [128] row max
    float* sI = sM + 128;                 // [128] row 1/sum

    const int q0   = blockIdx.x * 128;
    const int n    = blockIdx.y;
    const int t    = threadIdx.x;
    const int w    = t >> 5;            // 0..7
    const int lane = t & 31;

    float* attw = d_out + (size_t)ZSIZE + (size_t)n*SS*SS + (size_t)q0*SS;

    // ---- Phase 1: row stats (max, 1/sum), rows w*16 .. w*16+15
    for (int rr = 0; rr < 16; rr++){
        const int row = w*16 + rr;
        const float4* row4 = (const float4*)(attw + (size_t)row*SS);
        float4 v[16];
        float m = -3.4e38f;
#pragma unroll
        for (int c = 0; c < 16; c++){
            v[c] = row4[lane + 32*c];
            m = fmaxf(m, fmaxf(fmaxf(v[c].x, v[c].y), fmaxf(v[c].z, v[c].w)));
        }
#pragma unroll
        for (int o = 16; o > 0; o >>= 1) m = fmaxf(m, __shfl_xor_sync(0xffffffffu, m, o));
        float sum = 0.f;
#pragma unroll
        for (int c = 0; c < 16; c++){
            sum += __expf(v[c].x - m) + __expf(v[c].y - m)
                 + __expf(v[c].z - m) + __expf(v[c].w - m);
        }
#pragma unroll
        for (int o = 16; o > 0; o >>= 1) sum += __shfl_xor_sync(0xffffffffu, sum, o);
        if (lane == 0){ sM[row] = m; sI[row] = 1.0f / sum; }
    }
    __syncthreads();

    // ---- Phase 2: per 128-col block: normalize+write attn_w, P->smem, PV MMA
    const float* Vg = g_V + (size_t)n*SS*DKK;

    TFragC acc[4];
#pragma unroll
    for (int j = 0; j < 4; j++) wm::fill_fragment(acc[j], 0.0f);

    for (int kb = 0; kb < 16; kb++){
        // stage P block (read raw coalesced, exp, write final attn_w, smem P)
#pragma unroll
        for (int i = 0; i < 16; i++){
            int idx = i*256 + t;        // 0..4095 float4 (128 rows x 32 float4)
            int r = idx >> 5, c = idx & 31;
            float* gp = attw + (size_t)r*SS + kb*128 + c*4;
            float4 s = *(float4*)gp;
            float m = sM[r], inv = sI[r];
            float4 e;
            e.x = __expf(s.x - m) * inv;
            e.y = __expf(s.y - m) * inv;
            e.z = __expf(s.z - m) * inv;
            e.w = __expf(s.w - m) * inv;
            *(float4*)gp = e;                       // final attn_w (exact)
            e.x = f2tf32(e.x); e.y = f2tf32(e.y);
            e.z = f2tf32(e.z); e.w = f2tf32(e.w);
            *(float4*)(sP + r*PV_PLD + c*4) = e;    // tf32 P for MMA
        }
        // stage V block
#pragma unroll
        for (int i = 0; i < 8; i++){
            int idx = i*256 + t;        // 0..2047 float4 (128 rows x 16 float4)
            int r = idx >> 4, j = idx & 15;
            *(uint4*)(sV + r*PV_VLD + j*4) = *(const uint4*)(Vg + (size_t)(kb*128 + r)*DKK + j*4);
        }
        __syncthreads();

#pragma unroll
        for (int ks = 0; ks < 16; ks++){
            TFragA p;
            wm::load_matrix_sync(p, sP + (w*16)*PV_PLD + ks*8, PV_PLD);
#pragma unroll
            for (int j = 0; j < 4; j++){
                TFragBr vr;
                wm::load_matrix_sync(vr, sV + (ks*8)*PV_VLD + j*16, PV_VLD);
                wm::mma_sync(acc[j], p, vr, acc[j]);
            }
        }
        __syncthreads();
    }

    // epilogue: stage AO [128][68] in smem (reuse sP), split tf32 hi/lo, store
#pragma unroll
    for (int j = 0; j < 4; j++)
        wm::store_matrix_sync(sP + (w*16)*68 + j*16, acc[j], 68, wm::mem_row_major);
    __syncthreads();

#pragma unroll
    for (int i = 0; i < 32; i++){
        int idx = i*256 + t;            // 0..8191
        int q = idx >> 6, d = idx & 63;
        float vv = sP[q*68 + d];
        float hh = f2tf32(vv);
        size_t o = (size_t)(q0 + q)*(NH*DKK) + (size_t)n*DKK + d;
        g_AOh[o] = hh;
        g_AOl[o] = vv - hh;
    }
}

// ---------------------------------------------------------------------------
// Kernel 3: out-projection + transpose store (tf32 split-3).  (unchanged)
// ---------------------------------------------------------------------------
__global__ void __launch_bounds__(256) oproj_kernel(
        const float* __restrict__ bo, float* __restrict__ d_out)
{
    __shared__ __align__(128) float sbuf[64*132];

    const int r0 = blockIdx.x * 128;
    const int e0 = blockIdx.y * 64;
    const int t  = threadIdx.x;
    const int w  = t >> 5;
    const int wr = w >> 1;
    const int wc = w & 1;

    TFragC acc[2][2];
#pragma unroll
    for (int a=0;a<2;a++)
#pragma unroll
        for (int b2=0;b2<2;b2++) wm::fill_fragment(acc[a][b2], 0.0f);

    for (int ks = 0; ks < 64; ks++){
        TFragA ahi[2], alo[2];
#pragma unroll
        for (int mt = 0; mt < 2; mt++){
            size_t aofs = (size_t)(r0 + wr*32 + mt*16)*DMM + ks*8;
            wm::load_matrix_sync(ahi[mt], g_AOh + aofs, DMM);
            wm::load_matrix_sync(alo[mt], g_AOl + aofs, DMM);
        }
#pragma unroll
        for (int nt = 0; nt < 2; nt++){
            TFragBc bhi, blo;
            const int wofs = (e0 + wc*32 + nt*16)*DMM + ks*8;
            wm::load_matrix_sync(bhi, g_Woh + wofs, DMM);
            wm::load_matrix_sync(blo, g_Wol + wofs, DMM);
#pragma unroll
            for (int mt = 0; mt < 2; mt++){
                wm::mma_sync(acc[mt][nt], ahi[mt], bhi, acc[mt][nt]);
                wm::mma_sync(acc[mt][nt], ahi[mt], blo, acc[mt][nt]);
                wm::mma_sync(acc[mt][nt], alo[mt], bhi, acc[mt][nt]);
            }
        }
    }

#pragma unroll
    for (int mt = 0; mt < 2; mt++)
#pragma unroll
        for (int nt = 0; nt < 2; nt++)
            wm::store_matrix_sync(sbuf + (wc*32 + nt*16)*132 + wr*32 + mt*16,
                                  acc[mt][nt], 132, wm::mem_col_major);
    __syncthreads();

    const int b  = r0 >> 11;
    const int s0 = r0 & 2047;
#pragma unroll
    for (int it = 0; it < 32; it++){
        int el = it*2 + (t >> 7);
        int sl = t & 127;
        float v = sbuf[el*132 + sl] + bo[e0 + el];
        d_out[(size_t)b*(DIN_*SS) + (size_t)(e0 + el)*SS + s0 + sl] = v;
    }
}

// ---------------------------------------------------------------------------
extern "C" void kernel_launch(void* const* d_in, const int* in_sizes, int n_in,
                              void* d_out, int out_size)
{
    const float* x  = (const float*)d_in[0];
    const float* Wq = (const float*)d_in[1];
    const float* bq = (const float*)d_in[2];
    const float* Wk = (const float*)d_in[3];
    const float* bk = (const float*)d_in[4];
    const float* Wv = (const float*)d_in[5];
    const float* bv = (const float*)d_in[6];
    const float* Wo = (const float*)d_in[7];
    const float* bo = (const float*)d_in[8];
    float* out = (float*)d_out;

    bf16 *wqh, *wql, *wkh, *wkl, *wvh, *wvl;
    float *woh, *wol;
    cudaGetSymbolAddress((void**)&wqh, g_Wqbh); cudaGetSymbolAddress((void**)&wql, g_Wqbl);
    cudaGetSymbolAddress((void**)&wkh, g_Wkbh); cudaGetSymbolAddress((void**)&wkl, g_Wkbl);
    cudaGetSymbolAddress((void**)&wvh, g_Wvbh); cudaGetSymbolAddress((void**)&wvl, g_Wvbl);
    cudaGetSymbolAddress((void**)&woh, g_Woh);  cudaGetSymbolAddress((void**)&wol, g_Wol);

    const int nw = DMM * DIN_;   // 131072
    split_w_bf16<<<nw/256, 256>>>(Wq, wqh, wql, nw);
    split_w_bf16<<<nw/256, 256>>>(Wk, wkh, wkl, nw);
    split_w_bf16<<<nw/256, 256>>>(Wv, wvh, wvl, nw);
    split_w_f32 <<<nw/256, 256>>>(Wo, woh, wol, nw);

    const int score_smem = 4 * 128 * SK_LD * (int)sizeof(bf16);   // 73,728 B
    cudaFuncSetAttribute(score_kernel, cudaFuncAttributeMaxDynamicSharedMemorySize, score_smem);

    const int softpv_smem = (128*PV_PLD + 128*PV_VLD + 256) * (int)sizeof(float);  // 103,424 B
    cudaFuncSetAttribute(softpv_kernel, cudaFuncAttributeMaxDynamicSharedMemorySize, softpv_smem);

    qkv_kernel   <<<dim3(128, 4, 3), 256>>>(x, bq, bk, bv);
    score_kernel <<<dim3(16, 16, 32), 256, score_smem>>>(out);
    softpv_kernel<<<dim3(16, 32), 256, softpv_smem>>>(out);
    oproj_kernel <<<dim3(64, 4), 256>>>(bo, out);
}

// round 17
// speedup vs baseline: 1.0432x; 1.0432x over previous
#include <cuda_runtime.h>
#include <cuda_bf16.h>
#include <mma.h>
#include <cstdint>

namespace wm = nvcuda::wmma;

#define BB   4
#define DIN_ 256
#define SS   2048
#define DMM  512
#define HH   8
#define DKK  64
#define NH   32                      // B*H
#define ZSIZE (BB*DIN_*SS)           // 2097152
#define NKB  16                      // 2048/128 k-blocks

typedef __nv_bfloat16 bf16;

// ---- device-global scratch (allocation-free rule) -------------------------
__device__ bf16  g_Qbh[NH*SS*DKK], g_Qbl[NH*SS*DKK];
__device__ bf16  g_Kbh[NH*SS*DKK], g_Kbl[NH*SS*DKK];
__device__ float g_V  [NH*SS*DKK];                      // tf32-rounded values
__device__ float g_AOh[SS*NH*DKK], g_AOl[SS*NH*DKK];    // flat [S][B*H][dk]
__device__ bf16  g_Wqbh[DMM*DIN_], g_Wqbl[DMM*DIN_];
__device__ bf16  g_Wkbh[DMM*DIN_], g_Wkbl[DMM*DIN_];
__device__ bf16  g_Wvbh[DMM*DIN_], g_Wvbl[DMM*DIN_];
__device__ float g_Woh[DIN_*DMM],  g_Wol[DIN_*DMM];
__device__ float g_Smax[NH*NKB*SS], g_Ssum[NH*NKB*SS];  // per (n, kblock, q) stats

__device__ __forceinline__ float f2tf32(float x){
    float r; asm("cvt.rna.tf32.f32 %0, %1;" : "=f"(r) : "f"(x)); return r;
}

// bf16 fragments (m16n16k16)
using BFragA  = wm::fragment<wm::matrix_a,    16,16,16, bf16, wm::row_major>;
using BFragBc = wm::fragment<wm::matrix_b,    16,16,16, bf16, wm::col_major>;
using BFragC  = wm::fragment<wm::accumulator, 16,16,16, float>;
// tf32 fragments (m16n16k8)
using TFragA  = wm::fragment<wm::matrix_a,    16,16,8, wm::precision::tf32, wm::row_major>;
using TFragBc = wm::fragment<wm::matrix_b,    16,16,8, wm::precision::tf32, wm::col_major>;
using TFragBr = wm::fragment<wm::matrix_b,    16,16,8, wm::precision::tf32, wm::row_major>;
using TFragC  = wm::fragment<wm::accumulator, 16,16,8, float>;

// ---------------------------------------------------------------------------
// Kernel 0: all weight splits in one launch.  grid (512, 4).
// ---------------------------------------------------------------------------
__global__ void split_all_kernel(const float* __restrict__ Wq,
                                 const float* __restrict__ Wk,
                                 const float* __restrict__ Wv,
                                 const float* __restrict__ Wo)
{
    int i = blockIdx.x * 256 + threadIdx.x;      // 0..131071
    int which = blockIdx.y;
    if (which == 3){
        float v = Wo[i]; float hh = f2tf32(v);
        g_Woh[i] = hh; g_Wol[i] = v - hh;
    } else {
        const float* s = (which==0) ? Wq : (which==1 ? Wk : Wv);
        bf16* h = (which==0) ? g_Wqbh : (which==1 ? g_Wkbh : g_Wvbh);
        bf16* l = (which==0) ? g_Wqbl : (which==1 ? g_Wkbl : g_Wvbl);
        float v = s[i];
        bf16 hh = __float2bfloat16(v);
        h[i] = hh;
        l[i] = __float2bfloat16(v - __bfloat162float(hh));
    }
}

// ---------------------------------------------------------------------------
// Kernel 1: QKV projections, bf16x2 (3-product) emulated fp32.  (unchanged)
// ---------------------------------------------------------------------------
__global__ void __launch_bounds__(256) qkv_kernel(
        const float* __restrict__ x,
        const float* __restrict__ bq, const float* __restrict__ bk,
        const float* __restrict__ bv)
{
    __shared__ __align__(16) char sraw[64*132*4];
    bf16*  shi  = (bf16*)sraw;
    bf16*  slo  = shi + 64*40;
    float* sC   = (float*)sraw;

    const int which = blockIdx.z;
    const bf16* Wh    = (which==0) ? g_Wqbh : (which==1 ? g_Wkbh : g_Wvbh);
    const bf16* Wl    = (which==0) ? g_Wqbl : (which==1 ? g_Wkbl : g_Wvbl);
    const float* bias = (which==0) ? bq    : (which==1 ? bk    : bv);

    const int r0 = blockIdx.x * 64;
    const int m0 = blockIdx.y * 128;
    const int s0 = r0 >> 2;
    const int t  = threadIdx.x;
    const int w  = t >> 5;
    const int wr = w >> 2;
    const int wc = w & 3;

    BFragC acc[2][2];
#pragma unroll
    for (int a=0;a<2;a++)
#pragma unroll
        for (int b2=0;b2<2;b2++) wm::fill_fragment(acc[a][b2], 0.0f);

    for (int kc = 0; kc < DIN_; kc += 32){
#pragma unroll
        for (int j = 0; j < 8; j++){
            int idx = j*256 + t;
            int sl  = idx & 15;
            int p   = idx >> 4;
            int bb  = p & 3;
            int il  = p >> 2;
            float v = x[bb*(DIN_*SS) + (kc+il)*SS + (s0+sl)];
            bf16 h  = __float2bfloat16(v);
            int pos = (sl*4 + bb)*40 + il;
            shi[pos] = h;
            slo[pos] = __float2bfloat16(v - __bfloat162float(h));
        }
        __syncthreads();

#pragma unroll
        for (int ks = 0; ks < 2; ks++){
            BFragA ahi[2], alo[2];
#pragma unroll
            for (int mt = 0; mt < 2; mt++){
                wm::load_matrix_sync(ahi[mt], shi + (wr*32 + mt*16)*40 + ks*16, 40);
                wm::load_matrix_sync(alo[mt], slo + (wr*32 + mt*16)*40 + ks*16, 40);
            }
#pragma unroll
            for (int nt = 0; nt < 2; nt++){
                BFragBc bhi, blo;
                const int wofs = (m0 + wc*32 + nt*16)*DIN_ + kc + ks*16;
                wm::load_matrix_sync(bhi, Wh + wofs, DIN_);
                wm::load_matrix_sync(blo, Wl + wofs, DIN_);
#pragma unroll
                for (int mt = 0; mt < 2; mt++){
                    wm::mma_sync(acc[mt][nt], ahi[mt], bhi, acc[mt][nt]);
                    wm::mma_sync(acc[mt][nt], ahi[mt], blo, acc[mt][nt]);
                    wm::mma_sync(acc[mt][nt], alo[mt], bhi, acc[mt][nt]);
                }
            }
        }
        __syncthreads();
    }

#pragma unroll
    for (int mt = 0; mt < 2; mt++)
#pragma unroll
        for (int nt = 0; nt < 2; nt++)
            wm::store_matrix_sync(sC + (wr*32 + mt*16)*132 + wc*32 + nt*16,
                                  acc[mt][nt], 132, wm::mem_row_major);
    __syncthreads();

#pragma unroll
    for (int it = 0; it < 32; it++){
        int rl = it*2 + (t >> 7);
        int ml = t & 127;
        int m  = m0 + ml;
        float v = sC[rl*132 + ml] + bias[m];
        int s  = s0 + (rl >> 2);
        int bb = rl & 3;
        int h  = m >> 6;
        int d  = m & 63;
        size_t o = (size_t)((bb*HH + h)*SS + s)*DKK + d;
        if (which == 2){
            g_V[o] = f2tf32(v);           // tf32-exact V for 1-term PV
        } else {
            bf16 hh = __float2bfloat16(v);
            bf16 ll = __float2bfloat16(v - __bfloat162float(hh));
            if (which == 0){ g_Qbh[o] = hh; g_Qbl[o] = ll; }
            else           { g_Kbh[o] = hh; g_Kbl[o] = ll; }
        }
    }
}

// ---------------------------------------------------------------------------
// Kernel 2a: scores = Q K^T (bf16x2, 3 MMA/k16) + per-block softmax stats.
//   MMA core = R15 + A-fragment hoist.  Epilogue: C -> smem, per-row
//   (max, sumexp) over this 128-col block -> g_Smax/g_Ssum, then coalesced
//   float4 store of the raw-score block.
// CTA tile 128q x 128k, 8 warps.  grid (16,16,32), 72KB dyn smem, 2 CTA/SM.
// ---------------------------------------------------------------------------
#define SK_LD 72
__global__ void __launch_bounds__(256, 2) score_kernel(float* __restrict__ d_out)
{
    extern __shared__ __align__(16) bf16 sks[];
    bf16* sQh = sks;                    // [128][72]
    bf16* sQl = sQh + 128*SK_LD;
    bf16* sKh = sQl + 128*SK_LD;
    bf16* sKl = sKh + 128*SK_LD;
    float* sC = (float*)sks;            // epilogue reuse: [128][132]

    const int q0 = blockIdx.x * 128;
    const int k0 = blockIdx.y * 128;
    const int n  = blockIdx.z;
    const int t  = threadIdx.x;
    const int w  = t >> 5;
    const int wr = w >> 2;              // 0..1 -> 4 m-tiles each
    const int wc = w & 3;               // 0..3 -> 2 n-tiles each

    const bf16* Qhg = g_Qbh + ((size_t)n*SS + q0)*DKK;
    const bf16* Qlg = g_Qbl + ((size_t)n*SS + q0)*DKK;
    const bf16* Khg = g_Kbh + ((size_t)n*SS + k0)*DKK;
    const bf16* Klg = g_Kbl + ((size_t)n*SS + k0)*DKK;

#pragma unroll
    for (int i = 0; i < 4; i++){
        int idx = i*256 + t;            // 0..1023
        int r = idx >> 3, j = idx & 7;
        *(uint4*)(sQh + r*SK_LD + j*8) = *(const uint4*)(Qhg + r*DKK + j*8);
        *(uint4*)(sQl + r*SK_LD + j*8) = *(const uint4*)(Qlg + r*DKK + j*8);
        *(uint4*)(sKh + r*SK_LD + j*8) = *(const uint4*)(Khg + r*DKK + j*8);
        *(uint4*)(sKl + r*SK_LD + j*8) = *(const uint4*)(Klg + r*DKK + j*8);
    }
    __syncthreads();

    BFragC acc[4][2];
#pragma unroll
    for (int i=0;i<4;i++)
#pragma unroll
        for (int j=0;j<2;j++) wm::fill_fragment(acc[i][j], 0.0f);

#pragma unroll
    for (int ks = 0; ks < 4; ks++){
        BFragA ah[4], al[4];
#pragma unroll
        for (int i = 0; i < 4; i++){
            const int mtr = (wr*4 + i)*16;
            wm::load_matrix_sync(ah[i], sQh + mtr*SK_LD + ks*16, SK_LD);
            wm::load_matrix_sync(al[i], sQl + mtr*SK_LD + ks*16, SK_LD);
        }
#pragma unroll
        for (int j = 0; j < 2; j++){
            const int ntr = (wc*2 + j)*16;
            BFragBc bh, bl;
            wm::load_matrix_sync(bh, sKh + ntr*SK_LD + ks*16, SK_LD);
            wm::load_matrix_sync(bl, sKl + ntr*SK_LD + ks*16, SK_LD);
#pragma unroll
            for (int i = 0; i < 4; i++){
                wm::mma_sync(acc[i][j], ah[i], bh, acc[i][j]);
                wm::mma_sync(acc[i][j], ah[i], bl, acc[i][j]);
                wm::mma_sync(acc[i][j], al[i], bh, acc[i][j]);
            }
        }
    }
    __syncthreads();   // done reading staged tiles; reuse smem for C

#pragma unroll
    for (int i = 0; i < 4; i++)
#pragma unroll
        for (int j = 0; j < 2; j++)
            wm::store_matrix_sync(sC + (wr*4+i)*16*132 + (wc*2+j)*16,
                                  acc[i][j], 132, wm::mem_row_major);
    __syncthreads();

    // per-row block stats: 2 threads per row (halves of 64 cols each)
    {
        const int r  = t >> 1;
        const int hf = t & 1;
        const float4* rp = (const float4*)(sC + r*132 + hf*64);
        float m = -3.4e38f;
#pragma unroll
        for (int c = 0; c < 16; c++){
            float4 v = rp[c];
            m = fmaxf(m, fmaxf(fmaxf(v.x, v.y), fmaxf(v.z, v.w)));
        }
        m = fmaxf(m, __shfl_xor_sync(0xffffffffu, m, 1));
        float sum = 0.f;
#pragma unroll
        for (int c = 0; c < 16; c++){
            float4 v = rp[c];
            sum += __expf(v.x - m) + __expf(v.y - m)
                 + __expf(v.z - m) + __expf(v.w - m);
        }
        sum += __shfl_xor_sync(0xffffffffu, sum, 1);
        if (hf == 0){
            size_t so = (size_t)n*NKB*SS + (size_t)blockIdx.y*SS + q0 + r;
            g_Smax[so] = m;
            g_Ssum[so] = sum;
        }
    }

    // coalesced float4 write of the 128x128 raw-score block
    float* sco = d_out + (size_t)ZSIZE + (size_t)n*SS*SS + (size_t)q0*SS + k0;
#pragma unroll
    for (int it = 0; it < 16; it++){
        int idx = it*256 + t;           // 0..4095 float4
        int r = idx >> 5, c = idx & 31;
        *(float4*)(sco + (size_t)r*SS + c*4) = *(float4*)(sC + r*132 + c*4);
    }
}

// ---------------------------------------------------------------------------
// Kernel 2b: fused softmax + PV.  CTA = (head n, 128 q-rows), 256 threads.
//   Phase 1 (cheap): merge per-block stats -> row (max, 1/sum) in smem.
//   Phase 2: per 128-col block: coalesced raw read -> exp*inv -> coalesced
//            attn_w write; stage V; MMA from L1-hot attn_w fragments
//            (P rounded RNA-tf32; V already tf32 -> 1 MMA/k8).
// grid (16 q-tiles, 32 heads), 37.9KB static smem (R15 occupancy restored).
// ---------------------------------------------------------------------------
__global__ void __launch_bounds__(256) softpv_kernel(float* __restrict__ d_out)
{
    __shared__ __align__(16) float vst[128*SK_LD];     // V stage / AO stage
    __shared__ float sM[128], sI[128];

    const int q0   = blockIdx.x * 128;
    const int n    = blockIdx.y;
    const int t    = threadIdx.x;
    const int w    = t >> 5;            // 0..7

    float* attw = d_out + (size_t)ZSIZE + (size_t)n*SS*SS + (size_t)q0*SS;

    // ---- Phase 1: merge 16 per-block stats per row (threads 0..127)
    if (t < 128){
        const size_t sbase = (size_t)n*NKB*SS + q0 + t;
        float mb[NKB];
        float m = -3.4e38f;
#pragma unroll
        for (int b = 0; b < NKB; b++){
            mb[b] = g_Smax[sbase + (size_t)b*SS];
            m = fmaxf(m, mb[b]);
        }
        float sum = 0.f;
#pragma unroll
        for (int b = 0; b < NKB; b++)
            sum += g_Ssum[sbase + (size_t)b*SS] * __expf(mb[b] - m);
        sM[t] = m;
        sI[t] = 1.0f / sum;
    }
    __syncthreads();

    // ---- Phase 2: per 128-col block
    const float* Vg = g_V + (size_t)n*SS*DKK;

    TFragC acc[4];
#pragma unroll
    for (int j = 0; j < 4; j++) wm::fill_fragment(acc[j], 0.0f);

    for (int kb = 0; kb < NKB; kb++){
        // normalize this block in-place (raw -> final attn_w), coalesced
#pragma unroll
        for (int i = 0; i < 16; i++){
            int idx = i*256 + t;        // 0..4095 float4 (128 rows x 32 float4)
            int r = idx >> 5, c = idx & 31;
            float* gp = attw + (size_t)r*SS + kb*128 + c*4;
            float4 s = *(float4*)gp;
            float m = sM[r], inv = sI[r];
            float4 e;
            e.x = __expf(s.x - m) * inv;
            e.y = __expf(s.y - m) * inv;
            e.z = __expf(s.z - m) * inv;
            e.w = __expf(s.w - m) * inv;
            *(float4*)gp = e;
        }
        // stage V block
#pragma unroll
        for (int i = 0; i < 8; i++){
            int idx = i*256 + t;        // 0..2047 float4 (128 rows x 16 float4)
            int r = idx >> 4, j = idx & 15;
            *(uint4*)(vst + r*SK_LD + j*4) = *(const uint4*)(Vg + (size_t)(kb*128 + r)*DKK + j*4);
        }
        __syncthreads();                // orders attn_w writes + vst for MMA

#pragma unroll
        for (int ks = 0; ks < 16; ks++){
            TFragA p;
            wm::load_matrix_sync(p, attw + (size_t)(w*16)*SS + kb*128 + ks*8, SS);
#pragma unroll
            for (int e = 0; e < p.num_elements; e++) p.x[e] = f2tf32(p.x[e]);
#pragma unroll
            for (int j = 0; j < 4; j++){
                TFragBr vr;                       // V already tf32-exact
                wm::load_matrix_sync(vr, vst + (ks*8)*SK_LD + j*16, SK_LD);
                wm::mma_sync(acc[j], p, vr, acc[j]);
            }
        }
        __syncthreads();                // protect vst before next staging
    }

    // epilogue: stage AO [128][68] in smem, split to tf32 hi/lo, store flat
#pragma unroll
    for (int j = 0; j < 4; j++)
        wm::store_matrix_sync(vst + (w*16)*68 + j*16, acc[j], 68, wm::mem_row_major);
    __syncthreads();

#pragma unroll
    for (int i = 0; i < 32; i++){
        int idx = i*256 + t;            // 0..8191
        int q = idx >> 6, d = idx & 63;
        float vv = vst[q*68 + d];
        float hh = f2tf32(vv);
        size_t o = (size_t)(q0 + q)*(NH*DKK) + (size_t)n*DKK + d;
        g_AOh[o] = hh;
        g_AOl[o] = vv - hh;
    }
}

// ---------------------------------------------------------------------------
// Kernel 3: out-projection + transpose store (tf32 split-3).  (unchanged)
// ---------------------------------------------------------------------------
__global__ void __launch_bounds__(256) oproj_kernel(
        const float* __restrict__ bo, float* __restrict__ d_out)
{
    __shared__ __align__(128) float sbuf[64*132];

    const int r0 = blockIdx.x * 128;
    const int e0 = blockIdx.y * 64;
    const int t  = threadIdx.x;
    const int w  = t >> 5;
    const int wr = w >> 1;
    const int wc = w & 1;

    TFragC acc[2][2];
#pragma unroll
    for (int a=0;a<2;a++)
#pragma unroll
        for (int b2=0;b2<2;b2++) wm::fill_fragment(acc[a][b2], 0.0f);

    for (int ks = 0; ks < 64; ks++){
        TFragA ahi[2], alo[2];
#pragma unroll
        for (int mt = 0; mt < 2; mt++){
            size_t aofs = (size_t)(r0 + wr*32 + mt*16)*DMM + ks*8;
            wm::load_matrix_sync(ahi[mt], g_AOh + aofs, DMM);
            wm::load_matrix_sync(alo[mt], g_AOl + aofs, DMM);
        }
#pragma unroll
        for (int nt = 0; nt < 2; nt++){
            TFragBc bhi, blo;
            const int wofs = (e0 + wc*32 + nt*16)*DMM + ks*8;
            wm::load_matrix_sync(bhi, g_Woh + wofs, DMM);
            wm::load_matrix_sync(blo, g_Wol + wofs, DMM);
#pragma unroll
            for (int mt = 0; mt < 2; mt++){
                wm::mma_sync(acc[mt][nt], ahi[mt], bhi, acc[mt][nt]);
                wm::mma_sync(acc[mt][nt], ahi[mt], blo, acc[mt][nt]);
                wm::mma_sync(acc[mt][nt], alo[mt], bhi, acc[mt][nt]);
            }
        }
    }

#pragma unroll
    for (int mt = 0; mt < 2; mt++)
#pragma unroll
        for (int nt = 0; nt < 2; nt++)
            wm::store_matrix_sync(sbuf + (wc*32 + nt*16)*132 + wr*32 + mt*16,
                                  acc[mt][nt], 132, wm::mem_col_major);
    __syncthreads();

    const int b  = r0 >> 11;
    const int s0 = r0 & 2047;
#pragma unroll
    for (int it = 0; it < 32; it++){
        int el = it*2 + (t >> 7);
        int sl = t & 127;
        float v = sbuf[el*132 + sl] + bo[e0 + el];
        d_out[(size_t)b*(DIN_*SS) + (size_t)(e0 + el)*SS + s0 + sl] = v;
    }
}

// ---------------------------------------------------------------------------
extern "C" void kernel_launch(void* const* d_in, const int* in_sizes, int n_in,
                              void* d_out, int out_size)
{
    const float* x  = (const float*)d_in[0];
    const float* Wq = (const float*)d_in[1];
    const float* bq = (const float*)d_in[2];
    const float* Wk = (const float*)d_in[3];
    const float* bk = (const float*)d_in[4];
    const float* Wv = (const float*)d_in[5];
    const float* bv = (const float*)d_in[6];
    const float* Wo = (const float*)d_in[7];
    const float* bo = (const float*)d_in[8];
    float* out = (float*)d_out;

    split_all_kernel<<<dim3(512, 4), 256>>>(Wq, Wk, Wv, Wo);

    const int score_smem = 4 * 128 * SK_LD * (int)sizeof(bf16);   // 73,728 B
    cudaFuncSetAttribute(score_kernel, cudaFuncAttributeMaxDynamicSharedMemorySize, score_smem);

    qkv_kernel   <<<dim3(128, 4, 3), 256>>>(x, bq, bk, bv);
    score_kernel <<<dim3(16, 16, 32), 256, score_smem>>>(out);
    softpv_kernel<<<dim3(16, 32), 256>>>(out);
    oproj_kernel <<<dim3(64, 4), 256>>>(bo, out);
}